// round 1
// baseline (speedup 1.0000x reference)
#include <cuda_runtime.h>

#define NN 50000
#define EE 1600000

// Scratch (device globals; no allocations allowed)
__device__ __align__(16) float4 g_h [NN * 32];   // h = (1+eps)*x + agg, [N][128]
__device__ __align__(16) float4 g_h1[NN * 32];   // h @ W1 + b1
__device__ float g_sum[128];
__device__ float g_sumsq[128];
__device__ __align__(16) float g_scale[128];
__device__ __align__(16) float g_shift[128];

// ---------------------------------------------------------------------------
// Kernel 1: init accumulation buffer h = (1+eps)*x, zero BN stat accumulators
// ---------------------------------------------------------------------------
__global__ void init_kernel(const float4* __restrict__ x4, const float* __restrict__ eps) {
    int i = blockIdx.x * blockDim.x + threadIdx.x;
    if (i < 128) { g_sum[i] = 0.f; g_sumsq[i] = 0.f; }
    if (i < NN * 32) {
        float c = 1.0f + *eps;
        float4 v = x4[i];
        v.x *= c; v.y *= c; v.z *= c; v.w *= c;
        g_h[i] = v;
    }
}

// ---------------------------------------------------------------------------
// Kernel 2: per-edge message + scatter.  One warp per edge; lane handles 4
// floats (float4). m = relu(x[src] + sum of 3 bond embeddings); RED.128 into h[dst].
// ---------------------------------------------------------------------------
__global__ void edge_kernel(const float4* __restrict__ x4,
                            const int*    __restrict__ ea,
                            const int*    __restrict__ src,
                            const int*    __restrict__ dst,
                            const float4* __restrict__ be4) {
    int gt = blockIdx.x * blockDim.x + threadIdx.x;
    int e = gt >> 5;
    if (e >= EE) return;
    int lane = gt & 31;

    int s  = src[e];
    int d  = dst[e];
    int a0 = ea[e * 3 + 0];
    int a1 = ea[e * 3 + 1];
    int a2 = ea[e * 3 + 2];

    float4 xv = x4[s * 32 + lane];
    float4 e0 = be4[(a0     ) * 32 + lane];
    float4 e1 = be4[(a1 +  5) * 32 + lane];
    float4 e2 = be4[(a2 + 10) * 32 + lane];

    float4 m;
    m.x = fmaxf(xv.x + e0.x + e1.x + e2.x, 0.f);
    m.y = fmaxf(xv.y + e0.y + e1.y + e2.y, 0.f);
    m.z = fmaxf(xv.z + e0.z + e1.z + e2.z, 0.f);
    m.w = fmaxf(xv.w + e0.w + e1.w + e2.w, 0.f);

    atomicAdd(&g_h[d * 32 + lane], m);   // vector RED.128 (sm_90+)
}

// ---------------------------------------------------------------------------
// GEMM: out[r,:] = in[r,:] @ W + bias.  Block = 128 threads, 64 rows/block
// (4 tiles of 16 rows).  Whole W (64KB) in dynamic smem.  Thread = 4 rows x
// 4 cols microtile: per k-step 16 FFMA, 1 conflict-free LDS.128 + 4 broadcast
// LDS -> FMA-pipe bound.
// PASS 1: in = g_h, out = g_h1, accumulate per-column sum/sumsq.
// PASS 2: in = relu(g_h1*scale+shift) applied at load, out = d_out.
// ---------------------------------------------------------------------------
template <int PASS>
__global__ __launch_bounds__(128)
void gemm_kernel(const float* __restrict__ Wg,
                 const float* __restrict__ bias,
                 float*       __restrict__ outp) {
    extern __shared__ float sh[];
    float4* ws4 = (float4*)sh;             // 4096 float4 = W[128][128]
    float4* hb4 = (float4*)(sh + 16384);   // 512 float4  = 16 rows x 128
    __shared__ float ssum[128], ssq[128];

    const int t    = threadIdx.x;
    const int lane = t & 31;
    const int wrp  = t >> 5;

    if (PASS == 1) { ssum[t] = 0.f; ssq[t] = 0.f; }

    // Load full W into shared (coalesced float4)
    const float4* Wg4 = (const float4*)Wg;
#pragma unroll
    for (int i = 0; i < 32; i++) ws4[t + i * 128] = Wg4[t + i * 128];

    const float4* in4  = (PASS == 1) ? (const float4*)g_h : (const float4*)g_h1;
    float4*       out4 = (PASS == 1) ? (float4*)g_h1      : (float4*)outp;

    float4 tsum = make_float4(0, 0, 0, 0);
    float4 tssq = make_float4(0, 0, 0, 0);
    const float4 bv = ((const float4*)bias)[lane];

    const int rowbase = blockIdx.x * 64;

    for (int tile = 0; tile < 4; tile++) {
        int tb = rowbase + tile * 16;
        if (tb >= NN) break;                     // uniform across block
        __syncthreads();                         // hb4 reuse guard (also orders W load on tile 0)

        // Stage 16 input rows (BN+ReLU applied here on pass 2)
#pragma unroll
        for (int j = 0; j < 4; j++) {
            int p   = t + j * 128;
            int row = p >> 5, cp = p & 31;
            int gr  = tb + row;
            float4 v = make_float4(0, 0, 0, 0);
            if (gr < NN) v = in4[gr * 32 + cp];
            if (PASS == 2) {
                float4 a = ((const float4*)g_scale)[cp];
                float4 b = ((const float4*)g_shift)[cp];
                v.x = fmaxf(fmaf(v.x, a.x, b.x), 0.f);
                v.y = fmaxf(fmaf(v.y, a.y, b.y), 0.f);
                v.z = fmaxf(fmaf(v.z, a.z, b.z), 0.f);
                v.w = fmaxf(fmaf(v.w, a.w, b.w), 0.f);
            }
            hb4[p] = v;
        }
        __syncthreads();

        const float* h0 = sh + 16384 + (wrp * 4 + 0) * 128;
        const float* h1 = h0 + 128;
        const float* h2 = h0 + 256;
        const float* h3 = h0 + 384;

        float4 acc[4];
#pragma unroll
        for (int i = 0; i < 4; i++) acc[i] = make_float4(0, 0, 0, 0);

#pragma unroll 8
        for (int k = 0; k < 128; k++) {
            float4 wv = ws4[k * 32 + lane];
            float x0 = h0[k], x1 = h1[k], x2 = h2[k], x3 = h3[k];
            acc[0].x = fmaf(x0, wv.x, acc[0].x); acc[0].y = fmaf(x0, wv.y, acc[0].y);
            acc[0].z = fmaf(x0, wv.z, acc[0].z); acc[0].w = fmaf(x0, wv.w, acc[0].w);
            acc[1].x = fmaf(x1, wv.x, acc[1].x); acc[1].y = fmaf(x1, wv.y, acc[1].y);
            acc[1].z = fmaf(x1, wv.z, acc[1].z); acc[1].w = fmaf(x1, wv.w, acc[1].w);
            acc[2].x = fmaf(x2, wv.x, acc[2].x); acc[2].y = fmaf(x2, wv.y, acc[2].y);
            acc[2].z = fmaf(x2, wv.z, acc[2].z); acc[2].w = fmaf(x2, wv.w, acc[2].w);
            acc[3].x = fmaf(x3, wv.x, acc[3].x); acc[3].y = fmaf(x3, wv.y, acc[3].y);
            acc[3].z = fmaf(x3, wv.z, acc[3].z); acc[3].w = fmaf(x3, wv.w, acc[3].w);
        }

#pragma unroll
        for (int i = 0; i < 4; i++) {
            int gr = tb + wrp * 4 + i;
            if (gr < NN) {
                float4 o;
                o.x = acc[i].x + bv.x;
                o.y = acc[i].y + bv.y;
                o.z = acc[i].z + bv.z;
                o.w = acc[i].w + bv.w;
                out4[gr * 32 + lane] = o;
                if (PASS == 1) {
                    tsum.x += o.x; tsum.y += o.y; tsum.z += o.z; tsum.w += o.w;
                    tssq.x += o.x * o.x; tssq.y += o.y * o.y;
                    tssq.z += o.z * o.z; tssq.w += o.w * o.w;
                }
            }
        }
    }

    if (PASS == 1) {
        __syncthreads();
        atomicAdd(&ssum[4 * lane + 0], tsum.x);
        atomicAdd(&ssum[4 * lane + 1], tsum.y);
        atomicAdd(&ssum[4 * lane + 2], tsum.z);
        atomicAdd(&ssum[4 * lane + 3], tsum.w);
        atomicAdd(&ssq [4 * lane + 0], tssq.x);
        atomicAdd(&ssq [4 * lane + 1], tssq.y);
        atomicAdd(&ssq [4 * lane + 2], tssq.z);
        atomicAdd(&ssq [4 * lane + 3], tssq.w);
        __syncthreads();
        atomicAdd(&g_sum[t],   ssum[t]);
        atomicAdd(&g_sumsq[t], ssq[t]);
    }
}

// ---------------------------------------------------------------------------
// Kernel 4: BN stats -> affine (scale, shift).  128 threads.
// ---------------------------------------------------------------------------
__global__ void bn_finalize(const float* __restrict__ gamma, const float* __restrict__ beta) {
    int t = threadIdx.x;
    const float inv = 1.0f / (float)NN;
    float mean = g_sum[t] * inv;
    float var  = g_sumsq[t] * inv - mean * mean;
    float s = gamma[t] * rsqrtf(var + 1e-5f);
    g_scale[t] = s;
    g_shift[t] = beta[t] - mean * s;
}

// ---------------------------------------------------------------------------
extern "C" void kernel_launch(void* const* d_in, const int* in_sizes, int n_in,
                              void* d_out, int out_size) {
    const float* x     = (const float*)d_in[0];
    const int*   ea    = (const int*)  d_in[1];
    const int*   src   = (const int*)  d_in[2];
    const int*   dst   = (const int*)  d_in[3];
    const float* bond  = (const float*)d_in[4];
    const float* eps   = (const float*)d_in[5];
    const float* W1    = (const float*)d_in[6];
    const float* b1    = (const float*)d_in[7];
    const float* gamma = (const float*)d_in[8];
    const float* beta  = (const float*)d_in[9];
    const float* W2    = (const float*)d_in[10];
    const float* b2    = (const float*)d_in[11];

    const int SMEM = (16384 + 2048) * (int)sizeof(float);   // 73728 B
    cudaFuncSetAttribute(gemm_kernel<1>, cudaFuncAttributeMaxDynamicSharedMemorySize, SMEM);
    cudaFuncSetAttribute(gemm_kernel<2>, cudaFuncAttributeMaxDynamicSharedMemorySize, SMEM);

    init_kernel<<<(NN * 32 + 255) / 256, 256>>>((const float4*)x, eps);
    edge_kernel<<<(EE * 32 + 255) / 256, 256>>>((const float4*)x, ea, src, dst,
                                                (const float4*)bond);
    gemm_kernel<1><<<(NN + 63) / 64, 128, SMEM>>>(W1, b1, nullptr);
    bn_finalize<<<1, 128>>>(gamma, beta);
    gemm_kernel<2><<<(NN + 63) / 64, 128, SMEM>>>(W2, b2, (float*)d_out);
}

// round 2
// speedup vs baseline: 1.0506x; 1.0506x over previous
#include <cuda_runtime.h>

#define NN 50000
#define EE 1600000

// Scratch (device globals; no allocations allowed)
__device__ __align__(16) float4 g_h [NN * 32];   // h = (1+eps)*x + agg, [N][128]
__device__ __align__(16) float4 g_h1[NN * 32];   // h @ W1 + b1
__device__ float g_sum[128];
__device__ float g_sumsq[128];
__device__ __align__(16) float g_combo[125 * 128];   // all 5^3 bond-embedding sums

// ---------------------------------------------------------------------------
// Kernel 0: combo table — bond emb sums for all 125 attr combinations
// ---------------------------------------------------------------------------
__global__ void combo_kernel(const float* __restrict__ be) {
    int c = blockIdx.x, t = threadIdx.x;
    g_combo[c * 128 + t] = be[(c / 25) * 128 + t]
                         + be[(5 + (c / 5) % 5) * 128 + t]
                         + be[(10 + c % 5) * 128 + t];
}

// ---------------------------------------------------------------------------
// Kernel 1: init h = (1+eps)*x, zero BN stat accumulators
// ---------------------------------------------------------------------------
__global__ void init_kernel(const float4* __restrict__ x4, const float* __restrict__ eps) {
    int i = blockIdx.x * blockDim.x + threadIdx.x;
    if (i < 128) { g_sum[i] = 0.f; g_sumsq[i] = 0.f; }
    if (i < NN * 32) {
        float c = 1.0f + *eps;
        float4 v = x4[i];
        v.x *= c; v.y *= c; v.z *= c; v.w *= c;
        g_h[i] = v;
    }
}

// ---------------------------------------------------------------------------
// Kernel 2: per-edge message + scatter. One warp per edge; lane = float4.
// m = relu(x[src] + combo[code]); vector RED.128 into h[dst].
// ---------------------------------------------------------------------------
__global__ void edge_kernel(const float4* __restrict__ x4,
                            const int*    __restrict__ ea,
                            const int*    __restrict__ src,
                            const int*    __restrict__ dst) {
    int gt = blockIdx.x * blockDim.x + threadIdx.x;
    int e = gt >> 5;
    if (e >= EE) return;
    int lane = gt & 31;

    int s = src[e];
    int d = dst[e];
    int code = (ea[e * 3 + 0] * 5 + ea[e * 3 + 1]) * 5 + ea[e * 3 + 2];

    float4 xv = x4[s * 32 + lane];
    float4 ev = ((const float4*)g_combo)[code * 32 + lane];

    float4 m;
    m.x = fmaxf(xv.x + ev.x, 0.f);
    m.y = fmaxf(xv.y + ev.y, 0.f);
    m.z = fmaxf(xv.z + ev.z, 0.f);
    m.w = fmaxf(xv.w + ev.w, 0.f);

    atomicAdd(&g_h[d * 32 + lane], m);   // vector RED.128 (sm_90+)
}

// ---------------------------------------------------------------------------
// GEMM via packed fma.rn.f32x2 (FFMA2): out[r,:] = in[r,:] @ W + bias.
// Block = 128 threads (4 warps), 32 rows/block. W (64KB) in smem as float4;
// staged activations stored PRE-DUPLICATED as float2{v,v} so the inner loop
// needs no register duplication MOVs. Thread = 8 rows x 4 cols -> 16 FFMA2/k.
// PASS 1: in=g_h, out=g_h1, accumulate column sum/sumsq for BN.
// PASS 2: BN affine computed per-block from g_sum/g_sumsq; applied + ReLU at
//         stage time; out = d_out.
// ---------------------------------------------------------------------------
__device__ __forceinline__ float2 unpk(unsigned long long v) {
    float2 r;
    asm("mov.b64 {%0, %1}, %2;" : "=f"(r.x), "=f"(r.y) : "l"(v));
    return r;
}

template <int PASS>
__global__ __launch_bounds__(128)
void gemm_kernel(const float* __restrict__ Wg,
                 const float* __restrict__ bias,
                 float*       __restrict__ outp,
                 const float* __restrict__ gamma,
                 const float* __restrict__ beta) {
    extern __shared__ float sh[];
    // sh[0 .. 16384)          : W[128][128] (float4 view ws4)
    // sh[16384 .. 16384+8192) : hdup = float2[32 rows][128 k], value duplicated
    __shared__ __align__(16) float ssum[128];
    __shared__ __align__(16) float ssq[128];

    const int t    = threadIdx.x;
    const int lane = t & 31;
    const int wrp  = t >> 5;

    if (PASS == 1) { ssum[t] = 0.f; ssq[t] = 0.f; }
    if (PASS == 2) {
        // BN affine (redundant per block; 128 threads, trivial cost)
        const float inv = 1.0f / (float)NN;
        float mean = g_sum[t] * inv;
        float var  = g_sumsq[t] * inv - mean * mean;
        float s = gamma[t] * rsqrtf(var + 1e-5f);
        ssum[t] = s;                    // scale
        ssq[t]  = beta[t] - mean * s;   // shift
    }

    // Load full W into shared (coalesced float4)
    float4* ws4 = (float4*)sh;
    const float4* Wg4 = (const float4*)Wg;
#pragma unroll
    for (int i = 0; i < 32; i++) ws4[t + i * 128] = Wg4[t + i * 128];

    const float4* in4  = (PASS == 1) ? (const float4*)g_h : (const float4*)g_h1;
    float4*       out4 = (PASS == 1) ? (float4*)g_h1      : (float4*)outp;

    float2* hdup = (float2*)(sh + 16384);
    const int rowbase = blockIdx.x * 32;

    __syncthreads();   // ssum/ssq (pass2 affine) + W visible

    // Stage 32 rows, duplicated: hdup[row][col] = {v, v}
#pragma unroll
    for (int j = 0; j < 8; j++) {
        int p   = t + j * 128;
        int row = p >> 5, cp = p & 31;
        int gr  = rowbase + row;
        float4 v = make_float4(0, 0, 0, 0);
        if (gr < NN) v = in4[gr * 32 + cp];
        if (PASS == 2) {
            float4 a = *(const float4*)&ssum[cp * 4];
            float4 b = *(const float4*)&ssq[cp * 4];
            v.x = fmaxf(fmaf(v.x, a.x, b.x), 0.f);
            v.y = fmaxf(fmaf(v.y, a.y, b.y), 0.f);
            v.z = fmaxf(fmaf(v.z, a.z, b.z), 0.f);
            v.w = fmaxf(fmaf(v.w, a.w, b.w), 0.f);
        }
        float2* hp = &hdup[row * 128 + cp * 4];
        hp[0] = make_float2(v.x, v.x);
        hp[1] = make_float2(v.y, v.y);
        hp[2] = make_float2(v.z, v.z);
        hp[3] = make_float2(v.w, v.w);
    }
    __syncthreads();

    // Inner loop: 8 rows x 4 cols per thread, FFMA2
    const unsigned wbase = (unsigned)__cvta_generic_to_shared(sh);
    const unsigned waddr = wbase + lane * 16;                       // W[k][lane*4..]
    const unsigned hbase = wbase + 16384 * 4 + (wrp * 8) * 128 * 8; // this warp's rows

    unsigned long long acc[8][2];
#pragma unroll
    for (int r = 0; r < 8; r++) { acc[r][0] = 0ULL; acc[r][1] = 0ULL; }

#pragma unroll 4
    for (int k = 0; k < 128; k++) {
        unsigned long long wlo, whi;
        asm("ld.shared.v2.b64 {%0, %1}, [%2];"
            : "=l"(wlo), "=l"(whi) : "r"(waddr + k * 512));
#pragma unroll
        for (int r = 0; r < 8; r++) {
            unsigned long long xd;
            asm("ld.shared.b64 %0, [%1];"
                : "=l"(xd) : "r"(hbase + r * 1024 + k * 8));
            asm("fma.rn.f32x2 %0, %1, %2, %3;"
                : "=l"(acc[r][0]) : "l"(xd), "l"(wlo), "l"(acc[r][0]));
            asm("fma.rn.f32x2 %0, %1, %2, %3;"
                : "=l"(acc[r][1]) : "l"(xd), "l"(whi), "l"(acc[r][1]));
        }
    }

    // Epilogue: bias add, store, BN stats (pass 1)
    const float4 bv = ((const float4*)bias)[lane];
    float4 tsum = make_float4(0, 0, 0, 0);
    float4 tssq = make_float4(0, 0, 0, 0);

#pragma unroll
    for (int r = 0; r < 8; r++) {
        int gr = rowbase + wrp * 8 + r;
        if (gr < NN) {
            float2 lo = unpk(acc[r][0]);
            float2 hi = unpk(acc[r][1]);
            float4 o;
            o.x = lo.x + bv.x;
            o.y = lo.y + bv.y;
            o.z = hi.x + bv.z;
            o.w = hi.y + bv.w;
            out4[gr * 32 + lane] = o;
            if (PASS == 1) {
                tsum.x += o.x; tsum.y += o.y; tsum.z += o.z; tsum.w += o.w;
                tssq.x += o.x * o.x; tssq.y += o.y * o.y;
                tssq.z += o.z * o.z; tssq.w += o.w * o.w;
            }
        }
    }

    if (PASS == 1) {
        __syncthreads();
        atomicAdd(&ssum[4 * lane + 0], tsum.x);
        atomicAdd(&ssum[4 * lane + 1], tsum.y);
        atomicAdd(&ssum[4 * lane + 2], tsum.z);
        atomicAdd(&ssum[4 * lane + 3], tsum.w);
        atomicAdd(&ssq [4 * lane + 0], tssq.x);
        atomicAdd(&ssq [4 * lane + 1], tssq.y);
        atomicAdd(&ssq [4 * lane + 2], tssq.z);
        atomicAdd(&ssq [4 * lane + 3], tssq.w);
        __syncthreads();
        atomicAdd(&g_sum[t],   ssum[t]);
        atomicAdd(&g_sumsq[t], ssq[t]);
    }
}

// ---------------------------------------------------------------------------
extern "C" void kernel_launch(void* const* d_in, const int* in_sizes, int n_in,
                              void* d_out, int out_size) {
    const float* x     = (const float*)d_in[0];
    const int*   ea    = (const int*)  d_in[1];
    const int*   src   = (const int*)  d_in[2];
    const int*   dst   = (const int*)  d_in[3];
    const float* bond  = (const float*)d_in[4];
    const float* eps   = (const float*)d_in[5];
    const float* W1    = (const float*)d_in[6];
    const float* b1    = (const float*)d_in[7];
    const float* gamma = (const float*)d_in[8];
    const float* beta  = (const float*)d_in[9];
    const float* W2    = (const float*)d_in[10];
    const float* b2    = (const float*)d_in[11];

    const int SMEM = (16384 + 8192) * (int)sizeof(float);   // 98304 B
    cudaFuncSetAttribute(gemm_kernel<1>, cudaFuncAttributeMaxDynamicSharedMemorySize, SMEM);
    cudaFuncSetAttribute(gemm_kernel<2>, cudaFuncAttributeMaxDynamicSharedMemorySize, SMEM);

    combo_kernel<<<125, 128>>>(bond);
    init_kernel<<<(NN * 32 + 255) / 256, 256>>>((const float4*)x, eps);
    edge_kernel<<<(EE * 32 + 255) / 256, 256>>>((const float4*)x, ea, src, dst);
    gemm_kernel<1><<<(NN + 31) / 32, 128, SMEM>>>(W1, b1, nullptr, nullptr, nullptr);
    gemm_kernel<2><<<(NN + 31) / 32, 128, SMEM>>>(W2, b2, (float*)d_out, gamma, beta);
}

// round 3
// speedup vs baseline: 1.1903x; 1.1331x over previous
#include <cuda_runtime.h>

#define NN 50000
#define EE 1600000

// Scratch (device globals; no allocations allowed)
__device__ __align__(16) float4 g_h [NN * 32];     // h = (1+eps)*x + agg
__device__ __align__(16) float4 g_h1[NN * 32];     // h @ W1 + b1
__device__ float g_sum[128];
__device__ float g_sumsq[128];
__device__ __align__(16) float g_combo[125 * 128]; // all 5^3 bond-emb sums
__device__ int  g_deg[NN];
__device__ int  g_off[NN];
__device__ int  g_cur[NN];
__device__ __align__(16) int2 g_csr[EE];           // {src, combo_code} grouped by dst

// ---------------------------------------------------------------------------
__global__ void zero_kernel() {
    int i = blockIdx.x * blockDim.x + threadIdx.x;
    if (i < NN) g_deg[i] = 0;
    if (i < 128) { g_sum[i] = 0.f; g_sumsq[i] = 0.f; }
}

__global__ void combo_kernel(const float* __restrict__ be) {
    int c = blockIdx.x, t = threadIdx.x;
    g_combo[c * 128 + t] = be[(c / 25) * 128 + t]
                         + be[(5 + (c / 5) % 5) * 128 + t]
                         + be[(10 + c % 5) * 128 + t];
}

__global__ void hist_kernel(const int* __restrict__ dst) {
    int e = blockIdx.x * blockDim.x + threadIdx.x;
    if (e < EE) atomicAdd(&g_deg[dst[e]], 1);
}

// Exclusive scan of g_deg -> g_off (and g_cur). 1 block, 1024 threads.
__global__ void scan_kernel() {
    __shared__ int part[1024];
    const int CH = (NN + 1023) / 1024;   // 49
    int t = threadIdx.x;
    int base = t * CH;
    int s = 0;
    for (int i = 0; i < CH; i++) {
        int idx = base + i;
        if (idx < NN) s += g_deg[idx];
    }
    part[t] = s;
    __syncthreads();
    for (int off = 1; off < 1024; off <<= 1) {
        int v = (t >= off) ? part[t - off] : 0;
        __syncthreads();
        part[t] += v;
        __syncthreads();
    }
    int ex = part[t] - s;   // exclusive prefix for this chunk
    for (int i = 0; i < CH; i++) {
        int idx = base + i;
        if (idx < NN) { g_off[idx] = ex; g_cur[idx] = ex; ex += g_deg[idx]; }
    }
}

__global__ void scatter_kernel(const int* __restrict__ src,
                               const int* __restrict__ dst,
                               const int* __restrict__ ea) {
    int e = blockIdx.x * blockDim.x + threadIdx.x;
    if (e >= EE) return;
    int d = dst[e];
    int code = (ea[e * 3 + 0] * 5 + ea[e * 3 + 1]) * 5 + ea[e * 3 + 2];
    int pos = atomicAdd(&g_cur[d], 1);
    g_csr[pos] = make_int2(src[e], code);
}

// ---------------------------------------------------------------------------
// Aggregation: one warp per dst node. No atomics: accumulate in registers,
// write h = (1+eps)*x[v] + sum(relu(x[src]+combo)) once.
// ---------------------------------------------------------------------------
__global__ void agg_kernel(const float4* __restrict__ x4,
                           const float*  __restrict__ eps) {
    int gt = blockIdx.x * blockDim.x + threadIdx.x;
    int v = gt >> 5;
    if (v >= NN) return;
    int lane = gt & 31;

    const float4* cb4 = (const float4*)g_combo;
    int start = g_off[v];
    int deg   = g_deg[v];

    float4 acc = make_float4(0, 0, 0, 0);
    int i = 0;
    for (; i + 2 <= deg; i += 2) {
        int2 a = g_csr[start + i];
        int2 b = g_csr[start + i + 1];
        float4 xa = x4[a.x * 32 + lane];
        float4 ca = cb4[a.y * 32 + lane];
        float4 xb = x4[b.x * 32 + lane];
        float4 cb = cb4[b.y * 32 + lane];
        acc.x += fmaxf(xa.x + ca.x, 0.f) + fmaxf(xb.x + cb.x, 0.f);
        acc.y += fmaxf(xa.y + ca.y, 0.f) + fmaxf(xb.y + cb.y, 0.f);
        acc.z += fmaxf(xa.z + ca.z, 0.f) + fmaxf(xb.z + cb.z, 0.f);
        acc.w += fmaxf(xa.w + ca.w, 0.f) + fmaxf(xb.w + cb.w, 0.f);
    }
    if (i < deg) {
        int2 a = g_csr[start + i];
        float4 xa = x4[a.x * 32 + lane];
        float4 ca = cb4[a.y * 32 + lane];
        acc.x += fmaxf(xa.x + ca.x, 0.f);
        acc.y += fmaxf(xa.y + ca.y, 0.f);
        acc.z += fmaxf(xa.z + ca.z, 0.f);
        acc.w += fmaxf(xa.w + ca.w, 0.f);
    }

    float c = 1.0f + *eps;
    float4 xv = x4[v * 32 + lane];
    float4 h;
    h.x = fmaf(c, xv.x, acc.x);
    h.y = fmaf(c, xv.y, acc.y);
    h.z = fmaf(c, xv.z, acc.z);
    h.w = fmaf(c, xv.w, acc.w);
    g_h[v * 32 + lane] = h;
}

// ---------------------------------------------------------------------------
// GEMM via fma.rn.f32x2, even/odd-k packed accumulators.
// Block = 128 threads (4 warps), 64 rows/block (two 32-row halves).
// smem: Wt[128 cols][132 pitch] (transposed W, pitch 132 => conflict-free
// 16B lane accesses: 132 mod 32 == 4), xs[64 rows][128] natural floats.
// Thread microtile: 8 rows x 4 cols, cols = {lane, lane+32, lane+64, lane+96}.
// acc[r][cc] packs {sum over even k, sum over odd k}; x loaded as natural
// {x[k],x[k+1]} broadcast pairs (no duplication needed).
// PASS 1: in=g_h, out=g_h1, accumulate BN column stats.
// PASS 2: affine+ReLU applied at stage time from g_sum/g_sumsq; out=d_out.
// ---------------------------------------------------------------------------
#define WT_PITCH 132
#define WT_FLOATS (128 * WT_PITCH)          // 16896 floats = 67584 B
#define XS_OFF_B  (WT_FLOATS * 4)           // byte offset of xs in dyn smem
#define GEMM_SMEM (XS_OFF_B + 64 * 128 * 4) // 100352 B

__device__ __forceinline__ float2 unpk(unsigned long long v) {
    float2 r;
    asm("mov.b64 {%0, %1}, %2;" : "=f"(r.x), "=f"(r.y) : "l"(v));
    return r;
}

template <int PASS>
__global__ __launch_bounds__(128)
void gemm_kernel(const float* __restrict__ Wg,
                 const float* __restrict__ bias,
                 float*       __restrict__ outp,
                 const float* __restrict__ gamma,
                 const float* __restrict__ beta) {
    extern __shared__ float sh[];
    __shared__ __align__(16) float ssum[128];
    __shared__ __align__(16) float ssq[128];
    __shared__ __align__(16) float sa[128];   // BN scale (pass 2)
    __shared__ __align__(16) float sb[128];   // BN shift (pass 2)

    const int t    = threadIdx.x;
    const int lane = t & 31;
    const int wrp  = t >> 5;

    if (PASS == 1) { ssum[t] = 0.f; ssq[t] = 0.f; }
    if (PASS == 2) {
        const float inv = 1.0f / (float)NN;
        float mean = g_sum[t] * inv;
        float var  = g_sumsq[t] * inv - mean * mean;
        float s = gamma[t] * rsqrtf(var + 1e-5f);
        sa[t] = s;
        sb[t] = beta[t] - mean * s;
    }
    __syncthreads();   // sa/sb visible to stage loop

    // ---- Stage W transposed: Wt[c][k] = W[k][c], pitch 132 floats ----
    {
        const int c = t;   // 0..127
        for (int g = 0; g < 32; g++) {
            int k0 = g * 4;
            float w0 = Wg[(k0 + 0) * 128 + c];
            float w1 = Wg[(k0 + 1) * 128 + c];
            float w2 = Wg[(k0 + 2) * 128 + c];
            float w3 = Wg[(k0 + 3) * 128 + c];
            *(float4*)&sh[c * WT_PITCH + k0] = make_float4(w0, w1, w2, w3);
        }
    }

    // ---- Stage activations: xs[64][128] ----
    const float4* in4 = (PASS == 1) ? (const float4*)g_h : (const float4*)g_h1;
    float* xs = sh + WT_FLOATS;
    const int rowbase = blockIdx.x * 64;
#pragma unroll
    for (int j = 0; j < 16; j++) {
        int p = t + j * 128;
        int row = p >> 5, cp = p & 31;
        int gr = rowbase + row;
        float4 v = make_float4(0, 0, 0, 0);
        if (gr < NN) v = in4[gr * 32 + cp];
        if (PASS == 2) {
            float4 a = *(const float4*)&sa[cp * 4];
            float4 b = *(const float4*)&sb[cp * 4];
            v.x = fmaxf(fmaf(v.x, a.x, b.x), 0.f);
            v.y = fmaxf(fmaf(v.y, a.y, b.y), 0.f);
            v.z = fmaxf(fmaf(v.z, a.z, b.z), 0.f);
            v.w = fmaxf(fmaf(v.w, a.w, b.w), 0.f);
        }
        *(float4*)&xs[row * 128 + cp * 4] = v;
    }
    __syncthreads();

    float* out_f = (PASS == 1) ? (float*)g_h1 : outp;

    // bias per thread's 4 columns
    float bv[4];
#pragma unroll
    for (int cc = 0; cc < 4; cc++) bv[cc] = bias[lane + 32 * cc];

    const unsigned shb = (unsigned)__cvta_generic_to_shared(sh);
    unsigned wb[4];
#pragma unroll
    for (int cc = 0; cc < 4; cc++) wb[cc] = shb + (unsigned)((lane + 32 * cc) * WT_PITCH) * 4u;
    const unsigned xsb = shb + XS_OFF_B;

    float ts[4] = {0, 0, 0, 0};
    float tq[4] = {0, 0, 0, 0};

    for (int half = 0; half < 2; half++) {
        const int r0 = half * 32 + wrp * 8;
        unsigned xr[8];
#pragma unroll
        for (int r = 0; r < 8; r++) xr[r] = xsb + (unsigned)((r0 + r) * 128) * 4u;

        unsigned long long acc[8][4];
#pragma unroll
        for (int r = 0; r < 8; r++)
#pragma unroll
            for (int cc = 0; cc < 4; cc++) acc[r][cc] = 0ULL;

#pragma unroll 4
        for (int k = 0; k < 128; k += 4) {
            unsigned long long w01[4], w23[4];
#pragma unroll
            for (int cc = 0; cc < 4; cc++)
                asm("ld.shared.v2.b64 {%0, %1}, [%2];"
                    : "=l"(w01[cc]), "=l"(w23[cc]) : "r"(wb[cc] + (unsigned)(k * 4)));
#pragma unroll
            for (int r = 0; r < 8; r++) {
                unsigned long long x01, x23;
                asm("ld.shared.v2.b64 {%0, %1}, [%2];"
                    : "=l"(x01), "=l"(x23) : "r"(xr[r] + (unsigned)(k * 4)));
#pragma unroll
                for (int cc = 0; cc < 4; cc++) {
                    asm("fma.rn.f32x2 %0, %1, %2, %0;" : "+l"(acc[r][cc]) : "l"(x01), "l"(w01[cc]));
                    asm("fma.rn.f32x2 %0, %1, %2, %0;" : "+l"(acc[r][cc]) : "l"(x23), "l"(w23[cc]));
                }
            }
        }

        // Epilogue for this half
#pragma unroll
        for (int r = 0; r < 8; r++) {
            int gr = rowbase + r0 + r;
            if (gr < NN) {
#pragma unroll
                for (int cc = 0; cc < 4; cc++) {
                    float2 p = unpk(acc[r][cc]);
                    float o = p.x + p.y + bv[cc];
                    out_f[gr * 128 + lane + 32 * cc] = o;
                    if (PASS == 1) { ts[cc] += o; tq[cc] += o * o; }
                }
            }
        }
    }

    if (PASS == 1) {
#pragma unroll
        for (int cc = 0; cc < 4; cc++) {
            atomicAdd(&ssum[lane + 32 * cc], ts[cc]);
            atomicAdd(&ssq [lane + 32 * cc], tq[cc]);
        }
        __syncthreads();
        atomicAdd(&g_sum[t],   ssum[t]);
        atomicAdd(&g_sumsq[t], ssq[t]);
    }
}

// ---------------------------------------------------------------------------
extern "C" void kernel_launch(void* const* d_in, const int* in_sizes, int n_in,
                              void* d_out, int out_size) {
    const float* x     = (const float*)d_in[0];
    const int*   ea    = (const int*)  d_in[1];
    const int*   src   = (const int*)  d_in[2];
    const int*   dst   = (const int*)  d_in[3];
    const float* bond  = (const float*)d_in[4];
    const float* eps   = (const float*)d_in[5];
    const float* W1    = (const float*)d_in[6];
    const float* b1    = (const float*)d_in[7];
    const float* gamma = (const float*)d_in[8];
    const float* beta  = (const float*)d_in[9];
    const float* W2    = (const float*)d_in[10];
    const float* b2    = (const float*)d_in[11];

    cudaFuncSetAttribute(gemm_kernel<1>, cudaFuncAttributeMaxDynamicSharedMemorySize, GEMM_SMEM);
    cudaFuncSetAttribute(gemm_kernel<2>, cudaFuncAttributeMaxDynamicSharedMemorySize, GEMM_SMEM);

    zero_kernel<<<(NN + 255) / 256, 256>>>();
    combo_kernel<<<125, 128>>>(bond);
    hist_kernel<<<(EE + 255) / 256, 256>>>(dst);
    scan_kernel<<<1, 1024>>>();
    scatter_kernel<<<(EE + 255) / 256, 256>>>(src, dst, ea);
    agg_kernel<<<(NN * 32 + 255) / 256, 256>>>((const float4*)x, eps);
    gemm_kernel<1><<<(NN + 63) / 64, 128, GEMM_SMEM>>>(W1, b1, nullptr, nullptr, nullptr);
    gemm_kernel<2><<<(NN + 63) / 64, 128, GEMM_SMEM>>>(W2, b2, (float*)d_out, gamma, beta);
}

// round 4
// speedup vs baseline: 1.5721x; 1.3207x over previous
#include <cuda_runtime.h>

#define NN 50000
#define EE 1600000
#define SCAN_B 256
#define NBLK ((NN + SCAN_B - 1) / SCAN_B)   // 196

// Scratch (device globals; no allocations allowed)
__device__ __align__(16) float4 g_h [NN * 32];     // h = (1+eps)*x + agg
__device__ __align__(16) float4 g_h1[NN * 32];     // h @ W1 + b1
__device__ float g_sum[128];
__device__ float g_sumsq[128];
__device__ __align__(16) float g_combo[125 * 128]; // all 5^3 bond-emb sums
__device__ int  g_deg[NN];
__device__ int  g_off[NN];
__device__ int  g_cur[NN];
__device__ int  g_bsum[NBLK];
__device__ int  g_boff[NBLK];
__device__ __align__(16) int2 g_csr[EE];           // {src, combo_code} grouped by dst

// ---------------------------------------------------------------------------
__global__ void zero_kernel() {
    int i = blockIdx.x * blockDim.x + threadIdx.x;
    if (i < NN) g_deg[i] = 0;
    if (i < 128) { g_sum[i] = 0.f; g_sumsq[i] = 0.f; }
}

__global__ void combo_kernel(const float* __restrict__ be) {
    int c = blockIdx.x, t = threadIdx.x;
    g_combo[c * 128 + t] = be[(c / 25) * 128 + t]
                         + be[(5 + (c / 5) % 5) * 128 + t]
                         + be[(10 + c % 5) * 128 + t];
}

__global__ void hist_kernel(const int* __restrict__ dst) {
    int e = blockIdx.x * blockDim.x + threadIdx.x;
    if (e < EE) atomicAdd(&g_deg[dst[e]], 1);
}

// ---- Chip-wide 3-stage exclusive scan of g_deg -> g_off / g_cur ----------
__global__ void blocksum_kernel() {
    __shared__ int ws[8];
    int i = blockIdx.x * SCAN_B + threadIdx.x;
    int v = (i < NN) ? g_deg[i] : 0;
#pragma unroll
    for (int o = 16; o > 0; o >>= 1) v += __shfl_down_sync(0xffffffffu, v, o);
    if ((threadIdx.x & 31) == 0) ws[threadIdx.x >> 5] = v;
    __syncthreads();
    if (threadIdx.x < 8) {
        int s = ws[threadIdx.x];
#pragma unroll
        for (int o = 4; o > 0; o >>= 1) s += __shfl_down_sync(0xffu, s, o);
        if (threadIdx.x == 0) g_bsum[blockIdx.x] = s;
    }
}

__global__ void bscan_kernel() {   // one block of 256 threads, NBLK=196 values
    __shared__ int sh[SCAN_B];
    int t = threadIdx.x;
    int v = (t < NBLK) ? g_bsum[t] : 0;
    sh[t] = v;
    __syncthreads();
    for (int o = 1; o < SCAN_B; o <<= 1) {
        int u = (t >= o) ? sh[t - o] : 0;
        __syncthreads();
        sh[t] += u;
        __syncthreads();
    }
    if (t < NBLK) g_boff[t] = sh[t] - v;   // exclusive
}

__global__ void offsets_kernel() {
    __shared__ int ws[8];
    int t = threadIdx.x, lane = t & 31, w = t >> 5;
    int i = blockIdx.x * SCAN_B + t;
    int v = (i < NN) ? g_deg[i] : 0;
    // inclusive scan within warp
    int s = v;
#pragma unroll
    for (int o = 1; o < 32; o <<= 1) {
        int u = __shfl_up_sync(0xffffffffu, s, o);
        if (lane >= o) s += u;
    }
    if (lane == 31) ws[w] = s;
    __syncthreads();
    if (t < 8) {
        int a = ws[t];
#pragma unroll
        for (int o = 1; o < 8; o <<= 1) {
            int u = __shfl_up_sync(0xffu, a, o);
            if (t >= o) a += u;
        }
        ws[t] = a;
    }
    __syncthreads();
    int ex = s - v + (w ? ws[w - 1] : 0) + g_boff[blockIdx.x];
    if (i < NN) { g_off[i] = ex; g_cur[i] = ex; }
}

__global__ void scatter_kernel(const int* __restrict__ src,
                               const int* __restrict__ dst,
                               const int* __restrict__ ea) {
    int e = blockIdx.x * blockDim.x + threadIdx.x;
    if (e >= EE) return;
    int d = dst[e];
    int code = (ea[e * 3 + 0] * 5 + ea[e * 3 + 1]) * 5 + ea[e * 3 + 2];
    int pos = atomicAdd(&g_cur[d], 1);
    g_csr[pos] = make_int2(src[e], code);
}

// ---------------------------------------------------------------------------
// Aggregation: one warp per dst node. Register accumulation, single write.
// ---------------------------------------------------------------------------
__global__ void agg_kernel(const float4* __restrict__ x4,
                           const float*  __restrict__ eps) {
    int gt = blockIdx.x * blockDim.x + threadIdx.x;
    int v = gt >> 5;
    if (v >= NN) return;
    int lane = gt & 31;

    const float4* cb4 = (const float4*)g_combo;
    int start = g_off[v];
    int deg   = g_deg[v];

    float4 acc = make_float4(0, 0, 0, 0);
    int i = 0;
    for (; i + 2 <= deg; i += 2) {
        int2 a = g_csr[start + i];
        int2 b = g_csr[start + i + 1];
        float4 xa = x4[a.x * 32 + lane];
        float4 ca = cb4[a.y * 32 + lane];
        float4 xb = x4[b.x * 32 + lane];
        float4 cb = cb4[b.y * 32 + lane];
        acc.x += fmaxf(xa.x + ca.x, 0.f) + fmaxf(xb.x + cb.x, 0.f);
        acc.y += fmaxf(xa.y + ca.y, 0.f) + fmaxf(xb.y + cb.y, 0.f);
        acc.z += fmaxf(xa.z + ca.z, 0.f) + fmaxf(xb.z + cb.z, 0.f);
        acc.w += fmaxf(xa.w + ca.w, 0.f) + fmaxf(xb.w + cb.w, 0.f);
    }
    if (i < deg) {
        int2 a = g_csr[start + i];
        float4 xa = x4[a.x * 32 + lane];
        float4 ca = cb4[a.y * 32 + lane];
        acc.x += fmaxf(xa.x + ca.x, 0.f);
        acc.y += fmaxf(xa.y + ca.y, 0.f);
        acc.z += fmaxf(xa.z + ca.z, 0.f);
        acc.w += fmaxf(xa.w + ca.w, 0.f);
    }

    float c = 1.0f + *eps;
    float4 xv = x4[v * 32 + lane];
    float4 h;
    h.x = fmaf(c, xv.x, acc.x);
    h.y = fmaf(c, xv.y, acc.y);
    h.z = fmaf(c, xv.z, acc.z);
    h.w = fmaf(c, xv.w, acc.w);
    g_h[v * 32 + lane] = h;
}

// ---------------------------------------------------------------------------
// GEMM via fma.rn.f32x2, even/odd-k packed accumulators (as round 3).
// ---------------------------------------------------------------------------
#define WT_PITCH 132
#define WT_FLOATS (128 * WT_PITCH)
#define XS_OFF_B  (WT_FLOATS * 4)
#define GEMM_SMEM (XS_OFF_B + 64 * 128 * 4)

__device__ __forceinline__ float2 unpk(unsigned long long v) {
    float2 r;
    asm("mov.b64 {%0, %1}, %2;" : "=f"(r.x), "=f"(r.y) : "l"(v));
    return r;
}

template <int PASS>
__global__ __launch_bounds__(128)
void gemm_kernel(const float* __restrict__ Wg,
                 const float* __restrict__ bias,
                 float*       __restrict__ outp,
                 const float* __restrict__ gamma,
                 const float* __restrict__ beta) {
    extern __shared__ float sh[];
    __shared__ __align__(16) float ssum[128];
    __shared__ __align__(16) float ssq[128];
    __shared__ __align__(16) float sa[128];
    __shared__ __align__(16) float sb[128];

    const int t    = threadIdx.x;
    const int lane = t & 31;
    const int wrp  = t >> 5;

    if (PASS == 1) { ssum[t] = 0.f; ssq[t] = 0.f; }
    if (PASS == 2) {
        const float inv = 1.0f / (float)NN;
        float mean = g_sum[t] * inv;
        float var  = g_sumsq[t] * inv - mean * mean;
        float s = gamma[t] * rsqrtf(var + 1e-5f);
        sa[t] = s;
        sb[t] = beta[t] - mean * s;
    }
    __syncthreads();

    // Stage W transposed: Wt[c][k] = W[k][c], pitch 132
    {
        const int c = t;
        for (int g = 0; g < 32; g++) {
            int k0 = g * 4;
            float w0 = Wg[(k0 + 0) * 128 + c];
            float w1 = Wg[(k0 + 1) * 128 + c];
            float w2 = Wg[(k0 + 2) * 128 + c];
            float w3 = Wg[(k0 + 3) * 128 + c];
            *(float4*)&sh[c * WT_PITCH + k0] = make_float4(w0, w1, w2, w3);
        }
    }

    const float4* in4 = (PASS == 1) ? (const float4*)g_h : (const float4*)g_h1;
    float* xs = sh + WT_FLOATS;
    const int rowbase = blockIdx.x * 64;
#pragma unroll
    for (int j = 0; j < 16; j++) {
        int p = t + j * 128;
        int row = p >> 5, cp = p & 31;
        int gr = rowbase + row;
        float4 v = make_float4(0, 0, 0, 0);
        if (gr < NN) v = in4[gr * 32 + cp];
        if (PASS == 2) {
            float4 a = *(const float4*)&sa[cp * 4];
            float4 b = *(const float4*)&sb[cp * 4];
            v.x = fmaxf(fmaf(v.x, a.x, b.x), 0.f);
            v.y = fmaxf(fmaf(v.y, a.y, b.y), 0.f);
            v.z = fmaxf(fmaf(v.z, a.z, b.z), 0.f);
            v.w = fmaxf(fmaf(v.w, a.w, b.w), 0.f);
        }
        *(float4*)&xs[row * 128 + cp * 4] = v;
    }
    __syncthreads();

    float* out_f = (PASS == 1) ? (float*)g_h1 : outp;

    float bv[4];
#pragma unroll
    for (int cc = 0; cc < 4; cc++) bv[cc] = bias[lane + 32 * cc];

    const unsigned shb = (unsigned)__cvta_generic_to_shared(sh);
    unsigned wb[4];
#pragma unroll
    for (int cc = 0; cc < 4; cc++) wb[cc] = shb + (unsigned)((lane + 32 * cc) * WT_PITCH) * 4u;
    const unsigned xsb = shb + XS_OFF_B;

    float ts[4] = {0, 0, 0, 0};
    float tq[4] = {0, 0, 0, 0};

    for (int half = 0; half < 2; half++) {
        const int r0 = half * 32 + wrp * 8;
        unsigned xr[8];
#pragma unroll
        for (int r = 0; r < 8; r++) xr[r] = xsb + (unsigned)((r0 + r) * 128) * 4u;

        unsigned long long acc[8][4];
#pragma unroll
        for (int r = 0; r < 8; r++)
#pragma unroll
            for (int cc = 0; cc < 4; cc++) acc[r][cc] = 0ULL;

#pragma unroll 4
        for (int k = 0; k < 128; k += 4) {
            unsigned long long w01[4], w23[4];
#pragma unroll
            for (int cc = 0; cc < 4; cc++)
                asm("ld.shared.v2.b64 {%0, %1}, [%2];"
                    : "=l"(w01[cc]), "=l"(w23[cc]) : "r"(wb[cc] + (unsigned)(k * 4)));
#pragma unroll
            for (int r = 0; r < 8; r++) {
                unsigned long long x01, x23;
                asm("ld.shared.v2.b64 {%0, %1}, [%2];"
                    : "=l"(x01), "=l"(x23) : "r"(xr[r] + (unsigned)(k * 4)));
#pragma unroll
                for (int cc = 0; cc < 4; cc++) {
                    asm("fma.rn.f32x2 %0, %1, %2, %0;" : "+l"(acc[r][cc]) : "l"(x01), "l"(w01[cc]));
                    asm("fma.rn.f32x2 %0, %1, %2, %0;" : "+l"(acc[r][cc]) : "l"(x23), "l"(w23[cc]));
                }
            }
        }

#pragma unroll
        for (int r = 0; r < 8; r++) {
            int gr = rowbase + r0 + r;
            if (gr < NN) {
#pragma unroll
                for (int cc = 0; cc < 4; cc++) {
                    float2 p = unpk(acc[r][cc]);
                    float o = p.x + p.y + bv[cc];
                    out_f[gr * 128 + lane + 32 * cc] = o;
                    if (PASS == 1) { ts[cc] += o; tq[cc] += o * o; }
                }
            }
        }
    }

    if (PASS == 1) {
#pragma unroll
        for (int cc = 0; cc < 4; cc++) {
            atomicAdd(&ssum[lane + 32 * cc], ts[cc]);
            atomicAdd(&ssq [lane + 32 * cc], tq[cc]);
        }
        __syncthreads();
        atomicAdd(&g_sum[t],   ssum[t]);
        atomicAdd(&g_sumsq[t], ssq[t]);
    }
}

// ---------------------------------------------------------------------------
extern "C" void kernel_launch(void* const* d_in, const int* in_sizes, int n_in,
                              void* d_out, int out_size) {
    const float* x     = (const float*)d_in[0];
    const int*   ea    = (const int*)  d_in[1];
    const int*   src   = (const int*)  d_in[2];
    const int*   dst   = (const int*)  d_in[3];
    const float* bond  = (const float*)d_in[4];
    const float* eps   = (const float*)d_in[5];
    const float* W1    = (const float*)d_in[6];
    const float* b1    = (const float*)d_in[7];
    const float* gamma = (const float*)d_in[8];
    const float* beta  = (const float*)d_in[9];
    const float* W2    = (const float*)d_in[10];
    const float* b2    = (const float*)d_in[11];

    cudaFuncSetAttribute(gemm_kernel<1>, cudaFuncAttributeMaxDynamicSharedMemorySize, GEMM_SMEM);
    cudaFuncSetAttribute(gemm_kernel<2>, cudaFuncAttributeMaxDynamicSharedMemorySize, GEMM_SMEM);

    zero_kernel<<<(NN + 255) / 256, 256>>>();
    combo_kernel<<<125, 128>>>(bond);
    hist_kernel<<<(EE + 255) / 256, 256>>>(dst);
    blocksum_kernel<<<NBLK, SCAN_B>>>();
    bscan_kernel<<<1, SCAN_B>>>();
    offsets_kernel<<<NBLK, SCAN_B>>>();
    scatter_kernel<<<(EE + 255) / 256, 256>>>(src, dst, ea);
    agg_kernel<<<(NN * 32 + 255) / 256, 256>>>((const float4*)x, eps);
    gemm_kernel<1><<<(NN + 63) / 64, 128, GEMM_SMEM>>>(W1, b1, nullptr, nullptr, nullptr);
    gemm_kernel<2><<<(NN + 63) / 64, 128, GEMM_SMEM>>>(W2, b2, (float*)d_out, gamma, beta);
}